// round 2
// baseline (speedup 1.0000x reference)
#include <cuda_runtime.h>

#define NN     65536
#define EM     2097152
#define EGRID  524288
#define CI     128
#define NB     1024
#define NPG    64
#define NLAYER 7
#define NEVAL  5

// ---------------- scratch (device globals: allocation-free) ----------------
__device__ float g_h0[NN * CI];
__device__ float g_h1[NN * CI];
__device__ float g_agg1[NN * CI];
__device__ float g_agg2[NN * CI];
__device__ int   g_cnts1[NN];
__device__ int   g_cntr1[NN];
__device__ int   g_cnts2[NN];
__device__ int   g_cntr2[NN];
__device__ int   g_rowptr1[NN + 1];
__device__ int   g_rowptr2[NN + 1];
__device__ int   g_cursor1[NN];
__device__ int   g_cursor2[NN];
__device__ int   g_col1[EM];
__device__ int   g_col2[EGRID];
__device__ float g_s1[NN], g_r1[NN], g_s2[NN], g_r2[NN], g_t1[NN], g_t2[NN];
__device__ float g_W13[NLAYER * CI * CI];
__device__ float g_W23[NLAYER * CI * CI];
__device__ float g_c1[NLAYER * CI];
__device__ float g_c2[NLAYER * CI];
__device__ float g_v0[NB * CI];
__device__ float g_v1[NB * CI];
__device__ int   g_bsum[256];

// ---------------- preprocessing kernels ----------------
__global__ void k_zero_counts() {
    int i = blockIdx.x * blockDim.x + threadIdx.x;
    if (i < NN) { g_cnts1[i] = 0; g_cntr1[i] = 0; g_cnts2[i] = 0; g_cntr2[i] = 0; }
}

__global__ void k_hist(const int* __restrict__ snd, const int* __restrict__ rcv,
                       int gsel, int n) {
    int e = blockIdx.x * blockDim.x + threadIdx.x;
    if (e >= n) return;
    int* cs = (gsel == 1) ? g_cnts1 : g_cnts2;
    int* cr = (gsel == 1) ? g_cntr1 : g_cntr2;
    atomicAdd(&cs[snd[e]], 1);
    atomicAdd(&cr[rcv[e]], 1);
}

__global__ void k_norm(int gsel) {
    int i = blockIdx.x * blockDim.x + threadIdx.x;
    if (i >= NN) return;
    // +1 for self edge; degree >= 1 always, so max(d,1) is implicit
    if (gsel == 1) {
        g_s1[i] = rsqrtf((float)(g_cnts1[i] + 1));
        g_r1[i] = rsqrtf((float)(g_cntr1[i] + 1));
    } else {
        g_s2[i] = rsqrtf((float)(g_cnts2[i] + 1));
        g_r2[i] = rsqrtf((float)(g_cntr2[i] + 1));
    }
}

// 3-stage exclusive scan over 65536 ints (256 blocks x 256)
__global__ void k_scan1(int gsel) {
    const int* cnt = (gsel == 1) ? g_cntr1 : g_cntr2;
    __shared__ int sh[256];
    int tid = threadIdx.x;
    sh[tid] = cnt[blockIdx.x * 256 + tid];
    __syncthreads();
    for (int off = 128; off > 0; off >>= 1) {
        if (tid < off) sh[tid] += sh[tid + off];
        __syncthreads();
    }
    if (tid == 0) g_bsum[blockIdx.x] = sh[0];
}

__global__ void k_scan2() {
    __shared__ int sh[256];
    int tid = threadIdx.x;
    int v = g_bsum[tid];
    sh[tid] = v;
    __syncthreads();
    for (int off = 1; off < 256; off <<= 1) {
        int t = 0;
        if (tid >= off) t = sh[tid - off];
        __syncthreads();
        sh[tid] += t;
        __syncthreads();
    }
    g_bsum[tid] = sh[tid] - v;  // exclusive
}

__global__ void k_scan3(int gsel, int total) {
    const int* cnt = (gsel == 1) ? g_cntr1 : g_cntr2;
    int* rowptr    = (gsel == 1) ? g_rowptr1 : g_rowptr2;
    __shared__ int sh[256];
    int tid = threadIdx.x;
    int i = blockIdx.x * 256 + tid;
    int v = cnt[i];
    sh[tid] = v;
    __syncthreads();
    for (int off = 1; off < 256; off <<= 1) {
        int t = 0;
        if (tid >= off) t = sh[tid - off];
        __syncthreads();
        sh[tid] += t;
        __syncthreads();
    }
    rowptr[i] = sh[tid] - v + g_bsum[blockIdx.x];
    if (i == NN - 1) rowptr[NN] = total;
}

__global__ void k_cursor(int gsel) {
    int i = blockIdx.x * blockDim.x + threadIdx.x;
    if (i >= NN) return;
    if (gsel == 1) g_cursor1[i] = g_rowptr1[i];
    else           g_cursor2[i] = g_rowptr2[i];
}

__global__ void k_fill(const int* __restrict__ snd, const int* __restrict__ rcv,
                       int gsel, int n) {
    int e = blockIdx.x * blockDim.x + threadIdx.x;
    if (e >= n) return;
    int* cur = (gsel == 1) ? g_cursor1 : g_cursor2;
    int* col = (gsel == 1) ? g_col1    : g_col2;
    int pos = atomicAdd(&cur[rcv[e]], 1);
    col[pos] = snd[e];
}

// t[j] = r[j] * (s[j] + sum_{incoming e} s[src(e)])   (bias aggregation factor)
__global__ void k_tnorm(int gsel) {
    int j = blockIdx.x * blockDim.x + threadIdx.x;
    if (j >= NN) return;
    const int *rowptr, *col; const float *s, *r; float* t;
    if (gsel == 1) { rowptr = g_rowptr1; col = g_col1; s = g_s1; r = g_r1; t = g_t1; }
    else           { rowptr = g_rowptr2; col = g_col2; s = g_s2; r = g_r2; t = g_t2; }
    float acc = s[j];
    int k1 = rowptr[j + 1];
    for (int k = rowptr[j]; k < k1; ++k) acc += s[col[k]];
    t[j] = r[j] * acc;
}

// W13 = W1 @ W3_top, W23 = W2 @ W3_bot; c1 = b1 @ W3_top, c2 = b2 @ W3_bot
__global__ void k_fuse(const float* __restrict__ w1, const float* __restrict__ w2,
                       const float* __restrict__ b1, const float* __restrict__ b2,
                       const float* __restrict__ w3) {
    int l = blockIdx.x >> 7;
    int k = blockIdx.x & 127;
    int j = threadIdx.x;
    const float* w3l = w3 + l * 2 * CI * CI;
    const float* w1r = w1 + (l * CI + k) * CI;
    const float* w2r = w2 + (l * CI + k) * CI;
    float a1 = 0.f, a2 = 0.f;
    for (int m = 0; m < CI; ++m) {
        a1 += w1r[m] * w3l[m * CI + j];
        a2 += w2r[m] * w3l[(CI + m) * CI + j];
    }
    g_W13[(l * CI + k) * CI + j] = a1;
    g_W23[(l * CI + k) * CI + j] = a2;
    if (k == 0) {
        const float* b1r = b1 + l * CI;
        const float* b2r = b2 + l * CI;
        float c1 = 0.f, c2 = 0.f;
        for (int m = 0; m < CI; ++m) {
            c1 += b1r[m] * w3l[m * CI + j];
            c2 += b2r[m] * w3l[(CI + m) * CI + j];
        }
        g_c1[l * CI + j] = c1;
        g_c2[l * CI + j] = c2;
    }
}

__global__ void k_embed(const int* __restrict__ nodes, const float4* __restrict__ emb) {
    int i = blockIdx.x * blockDim.x + threadIdx.x;
    if (i >= NN * 32) return;
    int node = i >> 5, c = i & 31;
    ((float4*)g_h0)[i] = emb[nodes[node] * 32 + c];
}

// ---------------- per-layer aggregation: warp per node, CSR gather ----------------
__global__ void k_agg(int hsel, int gsel) {
    int gw = (blockIdx.x * blockDim.x + threadIdx.x) >> 5;
    if (gw >= NN) return;
    int lane = threadIdx.x & 31;
    const float4* h = (const float4*)(hsel ? g_h1 : g_h0);
    const int *rowptr, *col; const float *s, *r; float4* out;
    if (gsel == 1) { rowptr = g_rowptr1; col = g_col1; s = g_s1; r = g_r1; out = (float4*)g_agg1; }
    else           { rowptr = g_rowptr2; col = g_col2; s = g_s2; r = g_r2; out = (float4*)g_agg2; }

    float sv = s[gw];
    float4 hv = h[gw * 32 + lane];
    float ax = sv * hv.x, ay = sv * hv.y, az = sv * hv.z, aw = sv * hv.w;  // self edge
    int k = rowptr[gw], kend = rowptr[gw + 1];
    for (; k + 1 < kend; k += 2) {
        int i0 = col[k], i1 = col[k + 1];
        float f0 = s[i0], f1 = s[i1];
        float4 h0 = h[i0 * 32 + lane];
        float4 h1 = h[i1 * 32 + lane];
        ax += f0 * h0.x + f1 * h1.x;
        ay += f0 * h0.y + f1 * h1.y;
        az += f0 * h0.z + f1 * h1.z;
        aw += f0 * h0.w + f1 * h1.w;
    }
    if (k < kend) {
        int i0 = col[k];
        float f0 = s[i0];
        float4 h0 = h[i0 * 32 + lane];
        ax += f0 * h0.x; ay += f0 * h0.y; az += f0 * h0.z; aw += f0 * h0.w;
    }
    float rv = r[gw];
    out[gw * 32 + lane] = make_float4(rv * ax, rv * ay, rv * az, rv * aw);
}

// ---------------- fused GEMM: out = act(A1@Wa [+ A2@Wb + t-terms] + bias) ----------------
// BM=128, BN=128, BK=16; 256 threads, 8x8 microtile per thread.
template <bool TWO, bool RELU>
__global__ __launch_bounds__(256)
void k_gemm(int layer, int asel, int osel,
            const float* __restrict__ Wext, const float* __restrict__ bias) {
    constexpr int BK = 16;
    constexpr int ALD = 132;
    __shared__ __align__(16) float As1[BK * ALD];
    __shared__ __align__(16) float Ws1[BK * CI];
    __shared__ __align__(16) float As2[TWO ? BK * ALD : 4];
    __shared__ __align__(16) float Ws2[TWO ? BK * CI : 4];

    const float* A1;
    const float* A2 = nullptr;
    const float* Wa;
    const float* Wb = nullptr;
    if constexpr (TWO) {
        A1 = g_agg1; A2 = g_agg2;
        Wa = g_W13 + layer * CI * CI;
        Wb = g_W23 + layer * CI * CI;
    } else {
        A1 = (asel == 1) ? g_h1 : (asel == 2) ? g_v0 : g_v1;
        Wa = Wext;
    }
    float* out = (osel == 0) ? g_h0 : (osel == 1) ? g_h1 : (osel == 2) ? g_agg1
               : (osel == 3) ? g_v0 : g_v1;

    int tid  = threadIdx.x;
    int row0 = blockIdx.x * 128;
    int tcol = tid & 15;
    int trow = tid >> 4;

    float acc[8][8];
#pragma unroll
    for (int i = 0; i < 8; ++i)
#pragma unroll
        for (int j = 0; j < 8; ++j) acc[i][j] = 0.f;

    for (int k0 = 0; k0 < CI; k0 += BK) {
        __syncthreads();
#pragma unroll
        for (int it = 0; it < 2; ++it) {
            int idx = tid + it * 256;
            int r  = idx >> 2;
            int kc = (idx & 3) << 2;
            float4 v = *(const float4*)&A1[(row0 + r) * CI + k0 + kc];
            As1[(kc + 0) * ALD + r] = v.x;
            As1[(kc + 1) * ALD + r] = v.y;
            As1[(kc + 2) * ALD + r] = v.z;
            As1[(kc + 3) * ALD + r] = v.w;
            if constexpr (TWO) {
                float4 u = *(const float4*)&A2[(row0 + r) * CI + k0 + kc];
                As2[(kc + 0) * ALD + r] = u.x;
                As2[(kc + 1) * ALD + r] = u.y;
                As2[(kc + 2) * ALD + r] = u.z;
                As2[(kc + 3) * ALD + r] = u.w;
            }
        }
#pragma unroll
        for (int it = 0; it < 2; ++it) {
            int idx = tid + it * 256;
            int r = idx >> 5;
            int c = (idx & 31) << 2;
            *(float4*)&Ws1[r * CI + c] = *(const float4*)&Wa[(k0 + r) * CI + c];
            if constexpr (TWO)
                *(float4*)&Ws2[r * CI + c] = *(const float4*)&Wb[(k0 + r) * CI + c];
        }
        __syncthreads();
#pragma unroll
        for (int kk = 0; kk < BK; ++kk) {
            float a[8], b[8];
            *(float4*)&a[0] = *(const float4*)&As1[kk * ALD + trow * 8];
            *(float4*)&a[4] = *(const float4*)&As1[kk * ALD + trow * 8 + 4];
            *(float4*)&b[0] = *(const float4*)&Ws1[kk * CI + tcol * 8];
            *(float4*)&b[4] = *(const float4*)&Ws1[kk * CI + tcol * 8 + 4];
#pragma unroll
            for (int i = 0; i < 8; ++i)
#pragma unroll
                for (int j = 0; j < 8; ++j) acc[i][j] += a[i] * b[j];
            if constexpr (TWO) {
                *(float4*)&a[0] = *(const float4*)&As2[kk * ALD + trow * 8];
                *(float4*)&a[4] = *(const float4*)&As2[kk * ALD + trow * 8 + 4];
                *(float4*)&b[0] = *(const float4*)&Ws2[kk * CI + tcol * 8];
                *(float4*)&b[4] = *(const float4*)&Ws2[kk * CI + tcol * 8 + 4];
#pragma unroll
                for (int i = 0; i < 8; ++i)
#pragma unroll
                    for (int j = 0; j < 8; ++j) acc[i][j] += a[i] * b[j];
            }
        }
    }

    float bj[8], c1j[8], c2j[8];
#pragma unroll
    for (int j = 0; j < 8; ++j) bj[j] = bias[tcol * 8 + j];
    if constexpr (TWO) {
#pragma unroll
        for (int j = 0; j < 8; ++j) {
            c1j[j] = g_c1[layer * CI + tcol * 8 + j];
            c2j[j] = g_c2[layer * CI + tcol * 8 + j];
        }
    }
#pragma unroll
    for (int i = 0; i < 8; ++i) {
        int row = row0 + trow * 8 + i;
        float t1v = 0.f, t2v = 0.f;
        if constexpr (TWO) { t1v = g_t1[row]; t2v = g_t2[row]; }
        float o[8];
#pragma unroll
        for (int j = 0; j < 8; ++j) {
            float v = acc[i][j] + bj[j];
            if constexpr (TWO) v += t1v * c1j[j] + t2v * c2j[j];
            if constexpr (RELU) v = fmaxf(v, 0.f);
            o[j] = v;
        }
        *(float4*)&out[row * CI + tcol * 8]     = make_float4(o[0], o[1], o[2], o[3]);
        *(float4*)&out[row * CI + tcol * 8 + 4] = make_float4(o[4], o[5], o[6], o[7]);
    }
}

// ---------------- heads ----------------
__global__ void k_logits(const int* __restrict__ snd, const int* __restrict__ rcv,
                         float* __restrict__ out) {
    int e = (blockIdx.x * blockDim.x + threadIdx.x) >> 5;
    if (e >= EM) return;
    int lane = threadIdx.x & 31;
    const float4* lg = (const float4*)g_agg1;
    float4 a = lg[snd[e] * 32 + lane];
    float4 b = lg[rcv[e] * 32 + lane];
    float d = a.x * b.x + a.y * b.y + a.z * b.z + a.w * b.w;
#pragma unroll
    for (int off = 16; off > 0; off >>= 1) d += __shfl_xor_sync(0xffffffffu, d, off);
    if (lane == 0) out[e] = d;
}

__global__ void k_v0(const int* __restrict__ n_node) {
    int g = (blockIdx.x * blockDim.x + threadIdx.x) >> 5;
    if (g >= NB) return;
    int lane = threadIdx.x & 31;
    const float4* h = (const float4*)g_h1;
    int nn0 = n_node[0];
    float4 acc = make_float4(0.f, 0.f, 0.f, 0.f);
    for (int i = 0; i < NPG; ++i) {
        int gi = g * NPG + i;
        if (gi % nn0 == 0) continue;
        float4 v = h[gi * 32 + lane];
        acc.x += v.x; acc.y += v.y; acc.z += v.z; acc.w += v.w;
    }
    float inv = 1.f / (float)(n_node[g] - 1);
    ((float4*)g_v0)[g * 32 + lane] =
        make_float4(acc.x * inv, acc.y * inv, acc.z * inv, acc.w * inv);
}

__global__ void k_vout(const float* __restrict__ w_out, const float* __restrict__ b_out,
                       float* __restrict__ out) {
    int g = (blockIdx.x * blockDim.x + threadIdx.x) >> 5;
    if (g >= NB) return;
    int lane = threadIdx.x & 31;
    float d = 0.f;
#pragma unroll
    for (int c = lane; c < CI; c += 32) d += g_v1[g * CI + c] * w_out[c];
#pragma unroll
    for (int off = 16; off > 0; off >>= 1) d += __shfl_xor_sync(0xffffffffu, d, off);
    if (lane == 0) out[g] = tanhf(d + b_out[0]);
}

// ---------------- launch ----------------
extern "C" void kernel_launch(void* const* d_in, const int* in_sizes, int n_in,
                              void* d_out, int out_size) {
    const int*   nodes     = (const int*)d_in[0];
    const int*   senders   = (const int*)d_in[1];
    const int*   receivers = (const int*)d_in[2];
    const int*   gsnd      = (const int*)d_in[3];
    const int*   grcv      = (const int*)d_in[4];
    const int*   n_node    = (const int*)d_in[5];
    const float* emb       = (const float*)d_in[6];
    const float* w1        = (const float*)d_in[7];
    const float* b1        = (const float*)d_in[8];
    const float* w2        = (const float*)d_in[9];
    const float* b2        = (const float*)d_in[10];
    const float* w3        = (const float*)d_in[11];
    const float* b3        = (const float*)d_in[12];
    const float* w_logit   = (const float*)d_in[13];
    const float* b_logit   = (const float*)d_in[14];
    const float* eval_w    = (const float*)d_in[15];
    const float* eval_b    = (const float*)d_in[16];
    const float* w_out     = (const float*)d_in[17];
    const float* b_out     = (const float*)d_in[18];
    float* out = (float*)d_out;

    k_zero_counts<<<NN / 256, 256>>>();
    k_hist<<<EM / 256, 256>>>(senders, receivers, 1, EM);
    k_hist<<<EGRID / 256, 256>>>(gsnd, grcv, 2, EGRID);
    k_norm<<<NN / 256, 256>>>(1);
    k_norm<<<NN / 256, 256>>>(2);

    // CSR for move graph
    k_scan1<<<256, 256>>>(1);
    k_scan2<<<1, 256>>>();
    k_scan3<<<256, 256>>>(1, EM);
    k_cursor<<<NN / 256, 256>>>(1);
    k_fill<<<EM / 256, 256>>>(senders, receivers, 1, EM);
    // CSR for grid graph
    k_scan1<<<256, 256>>>(2);
    k_scan2<<<1, 256>>>();
    k_scan3<<<256, 256>>>(2, EGRID);
    k_cursor<<<NN / 256, 256>>>(2);
    k_fill<<<EGRID / 256, 256>>>(gsnd, grcv, 2, EGRID);

    k_tnorm<<<NN / 256, 256>>>(1);
    k_tnorm<<<NN / 256, 256>>>(2);
    k_fuse<<<NLAYER * CI, CI>>>(w1, w2, b1, b2, w3);
    k_embed<<<(NN * 32) / 256, 256>>>(nodes, (const float4*)emb);

    for (int i = 0; i < NLAYER; ++i) {
        k_agg<<<NN / 8, 256>>>(i & 1, 1);
        k_agg<<<NN / 8, 256>>>(i & 1, 2);
        k_gemm<true, true><<<NN / 128, 256>>>(i, 0, 1 - (i & 1), nullptr, b3 + i * CI);
    }

    // logits head: lg = h @ w_logit + b_logit  -> g_agg1
    k_gemm<false, false><<<NN / 128, 256>>>(0, 1, 2, w_logit, b_logit);
    k_logits<<<EM / 8, 256>>>(senders, receivers, out);

    // value head
    k_v0<<<NB / 8, 256>>>(n_node);
    for (int l = 0; l < NEVAL; ++l) {
        k_gemm<false, true><<<NB / 128, 256>>>(0, 2 + (l & 1), 4 - (l & 1),
                                               eval_w + l * CI * CI, eval_b + l * CI);
    }
    k_vout<<<NB / 8, 256>>>(w_out, b_out, out + EM);
}

// round 4
// speedup vs baseline: 1.2118x; 1.2118x over previous
#include <cuda_runtime.h>
#include <cuda_bf16.h>
#include <mma.h>
using namespace nvcuda;

#define NN     65536
#define EM     2097152
#define EGRID  524288
#define CI     128
#define NB     1024
#define NPG    64
#define NLAYER 7
#define NEVAL  5

// ---------------- scratch (device globals: allocation-free) ----------------
__device__ float g_h0[NN * CI];
__device__ float g_h1[NN * CI];
__device__ float g_agg1[NN * CI];
__device__ float g_agg2[NN * CI];
__device__ int   g_cnts1[NN];
__device__ int   g_cntr1[NN];
__device__ int   g_cnts2[NN];
__device__ int   g_cntr2[NN];
__device__ int   g_rowptr1[NN + 1];
__device__ int   g_rowptr2[NN + 1];
__device__ int   g_cursor1[NN];
__device__ int   g_cursor2[NN];
__device__ int   g_col1[EM];
__device__ int   g_col2[EGRID];
__device__ float g_s1[NN], g_r1[NN], g_s2[NN], g_r2[NN], g_t1[NN], g_t2[NN];
__device__ float g_W13[NLAYER * CI * CI];
__device__ float g_W23[NLAYER * CI * CI];
__device__ float g_c1[NLAYER * CI];
__device__ float g_c2[NLAYER * CI];
__device__ float g_v0[NB * CI];
__device__ float g_v1[NB * CI];
__device__ int   g_bsum[256];

// ---------------- preprocessing kernels ----------------
__global__ void k_zero_counts() {
    int i = blockIdx.x * blockDim.x + threadIdx.x;
    if (i < NN) { g_cnts1[i] = 0; g_cntr1[i] = 0; g_cnts2[i] = 0; g_cntr2[i] = 0; }
}

__global__ void k_hist(const int* __restrict__ snd, const int* __restrict__ rcv,
                       int gsel, int n) {
    int e = blockIdx.x * blockDim.x + threadIdx.x;
    if (e >= n) return;
    int* cs = (gsel == 1) ? g_cnts1 : g_cnts2;
    int* cr = (gsel == 1) ? g_cntr1 : g_cntr2;
    atomicAdd(&cs[snd[e]], 1);
    atomicAdd(&cr[rcv[e]], 1);
}

__global__ void k_norm(int gsel) {
    int i = blockIdx.x * blockDim.x + threadIdx.x;
    if (i >= NN) return;
    if (gsel == 1) {
        g_s1[i] = rsqrtf((float)(g_cnts1[i] + 1));
        g_r1[i] = rsqrtf((float)(g_cntr1[i] + 1));
    } else {
        g_s2[i] = rsqrtf((float)(g_cnts2[i] + 1));
        g_r2[i] = rsqrtf((float)(g_cntr2[i] + 1));
    }
}

// 3-stage exclusive scan over 65536 ints
__global__ void k_scan1(int gsel) {
    const int* cnt = (gsel == 1) ? g_cntr1 : g_cntr2;
    __shared__ int sh[256];
    int tid = threadIdx.x;
    sh[tid] = cnt[blockIdx.x * 256 + tid];
    __syncthreads();
    for (int off = 128; off > 0; off >>= 1) {
        if (tid < off) sh[tid] += sh[tid + off];
        __syncthreads();
    }
    if (tid == 0) g_bsum[blockIdx.x] = sh[0];
}

__global__ void k_scan2() {
    __shared__ int sh[256];
    int tid = threadIdx.x;
    int v = g_bsum[tid];
    sh[tid] = v;
    __syncthreads();
    for (int off = 1; off < 256; off <<= 1) {
        int t = 0;
        if (tid >= off) t = sh[tid - off];
        __syncthreads();
        sh[tid] += t;
        __syncthreads();
    }
    g_bsum[tid] = sh[tid] - v;  // exclusive
}

__global__ void k_scan3(int gsel, int total) {
    const int* cnt = (gsel == 1) ? g_cntr1 : g_cntr2;
    int* rowptr    = (gsel == 1) ? g_rowptr1 : g_rowptr2;
    __shared__ int sh[256];
    int tid = threadIdx.x;
    int i = blockIdx.x * 256 + tid;
    int v = cnt[i];
    sh[tid] = v;
    __syncthreads();
    for (int off = 1; off < 256; off <<= 1) {
        int t = 0;
        if (tid >= off) t = sh[tid - off];
        __syncthreads();
        sh[tid] += t;
        __syncthreads();
    }
    rowptr[i] = sh[tid] - v + g_bsum[blockIdx.x];
    if (i == NN - 1) rowptr[NN] = total;
}

__global__ void k_cursor(int gsel) {
    int i = blockIdx.x * blockDim.x + threadIdx.x;
    if (i >= NN) return;
    if (gsel == 1) g_cursor1[i] = g_rowptr1[i];
    else           g_cursor2[i] = g_rowptr2[i];
}

__global__ void k_fill(const int* __restrict__ snd, const int* __restrict__ rcv,
                       int gsel, int n) {
    int e = blockIdx.x * blockDim.x + threadIdx.x;
    if (e >= n) return;
    int* cur = (gsel == 1) ? g_cursor1 : g_cursor2;
    int* col = (gsel == 1) ? g_col1    : g_col2;
    int pos = atomicAdd(&cur[rcv[e]], 1);
    col[pos] = snd[e];
}

// t[j] = r[j] * (s[j] + sum_{incoming e} s[src(e)])
__global__ void k_tnorm(int gsel) {
    int j = blockIdx.x * blockDim.x + threadIdx.x;
    if (j >= NN) return;
    const int *rowptr, *col; const float *s, *r; float* t;
    if (gsel == 1) { rowptr = g_rowptr1; col = g_col1; s = g_s1; r = g_r1; t = g_t1; }
    else           { rowptr = g_rowptr2; col = g_col2; s = g_s2; r = g_r2; t = g_t2; }
    float acc = s[j];
    int k1 = rowptr[j + 1];
    for (int k = rowptr[j]; k < k1; ++k) acc += s[col[k]];
    t[j] = r[j] * acc;
}

// W13 = W1 @ W3_top, W23 = W2 @ W3_bot; c1 = b1 @ W3_top, c2 = b2 @ W3_bot
__global__ void k_fuse(const float* __restrict__ w1, const float* __restrict__ w2,
                       const float* __restrict__ b1, const float* __restrict__ b2,
                       const float* __restrict__ w3) {
    int l = blockIdx.x >> 7;
    int k = blockIdx.x & 127;
    int j = threadIdx.x;
    const float* w3l = w3 + l * 2 * CI * CI;
    const float* w1r = w1 + (l * CI + k) * CI;
    const float* w2r = w2 + (l * CI + k) * CI;
    float a1 = 0.f, a2 = 0.f;
    for (int m = 0; m < CI; ++m) {
        a1 += w1r[m] * w3l[m * CI + j];
        a2 += w2r[m] * w3l[(CI + m) * CI + j];
    }
    g_W13[(l * CI + k) * CI + j] = a1;
    g_W23[(l * CI + k) * CI + j] = a2;
    if (k == 0) {
        const float* b1r = b1 + l * CI;
        const float* b2r = b2 + l * CI;
        float c1 = 0.f, c2 = 0.f;
        for (int m = 0; m < CI; ++m) {
            c1 += b1r[m] * w3l[m * CI + j];
            c2 += b2r[m] * w3l[(CI + m) * CI + j];
        }
        g_c1[l * CI + j] = c1;
        g_c2[l * CI + j] = c2;
    }
}

__global__ void k_embed(const int* __restrict__ nodes, const float4* __restrict__ emb) {
    int i = blockIdx.x * blockDim.x + threadIdx.x;
    if (i >= NN * 32) return;
    int node = i >> 5, c = i & 31;
    ((float4*)g_h0)[i] = emb[nodes[node] * 32 + c];
}

// ---------------- aggregation: warp per node, both graphs in one launch ----------------
__device__ __forceinline__ void agg_node(int gw, int lane, const float4* __restrict__ h,
                                         const int* __restrict__ rowptr,
                                         const int* __restrict__ col,
                                         const float* __restrict__ s,
                                         const float* __restrict__ r,
                                         float4* __restrict__ out) {
    float sv = s[gw];
    float4 hv = h[gw * 32 + lane];
    float ax = sv * hv.x, ay = sv * hv.y, az = sv * hv.z, aw = sv * hv.w;  // self edge
    int k = rowptr[gw], kend = rowptr[gw + 1];
    for (; k + 1 < kend; k += 2) {
        int i0 = col[k], i1 = col[k + 1];
        float f0 = s[i0], f1 = s[i1];
        float4 h0 = h[i0 * 32 + lane];
        float4 h1 = h[i1 * 32 + lane];
        ax += f0 * h0.x + f1 * h1.x;
        ay += f0 * h0.y + f1 * h1.y;
        az += f0 * h0.z + f1 * h1.z;
        aw += f0 * h0.w + f1 * h1.w;
    }
    if (k < kend) {
        int i0 = col[k];
        float f0 = s[i0];
        float4 h0 = h[i0 * 32 + lane];
        ax += f0 * h0.x; ay += f0 * h0.y; az += f0 * h0.z; aw += f0 * h0.w;
    }
    float rv = r[gw];
    out[gw * 32 + lane] = make_float4(rv * ax, rv * ay, rv * az, rv * aw);
}

__global__ void k_agg_both(int hsel) {
    int gw = (blockIdx.x * blockDim.x + threadIdx.x) >> 5;
    int lane = threadIdx.x & 31;
    const float4* h = (const float4*)(hsel ? g_h1 : g_h0);
    if (gw < NN) {
        agg_node(gw, lane, h, g_rowptr1, g_col1, g_s1, g_r1, (float4*)g_agg1);
    } else {
        gw -= NN;
        if (gw >= NN) return;
        agg_node(gw, lane, h, g_rowptr2, g_col2, g_s2, g_r2, (float4*)g_agg2);
    }
}

// ---------------- bf16 split tensor-core GEMM (3-MMA compensated) ----------------
// out = A1@Wa [+ A2@Wb], fp32-accurate via hi/lo bf16 decomposition.
// BM=128, BN=128, BK=16; 256 threads = 8 warps; each warp computes 32x64.
__device__ __forceinline__ void split2(float x, __nv_bfloat16& hi, __nv_bfloat16& lo) {
    hi = __float2bfloat16_rn(x);
    lo = __float2bfloat16_rn(x - __bfloat162float(hi));
}

template <bool TWO>
__global__ __launch_bounds__(256)
void k_gemm_tc(int layer, int asel, int osel, const float* __restrict__ Wext) {
    constexpr int BK  = 16;
    constexpr int ALD = 24;   // bf16 elems per padded A row
    constexpr int WLD = 136;  // bf16 elems per padded W row
    __shared__ __align__(16) __nv_bfloat16 As1h[128 * ALD], As1l[128 * ALD];
    __shared__ __align__(16) __nv_bfloat16 Ws1h[BK * WLD],  Ws1l[BK * WLD];
    __shared__ __align__(16) __nv_bfloat16 As2h[TWO ? 128 * ALD : 8], As2l[TWO ? 128 * ALD : 8];
    __shared__ __align__(16) __nv_bfloat16 Ws2h[TWO ? BK * WLD : 8],  Ws2l[TWO ? BK * WLD : 8];

    const float* A1;
    const float* A2 = nullptr;
    const float* Wa;
    const float* Wb = nullptr;
    if constexpr (TWO) {
        A1 = g_agg1; A2 = g_agg2;
        Wa = g_W13 + layer * CI * CI;
        Wb = g_W23 + layer * CI * CI;
    } else {
        A1 = (asel == 1) ? g_h1 : (asel == 2) ? g_v0 : g_v1;
        Wa = Wext;
    }
    float* out = (osel == 0) ? g_h0 : (osel == 1) ? g_h1 : (osel == 2) ? g_agg1
               : (osel == 3) ? g_v0 : g_v1;

    int tid  = threadIdx.x;
    int row0 = blockIdx.x * 128;
    int wid  = tid >> 5;
    int wm   = wid & 3;    // row block of 32
    int wn   = wid >> 2;   // col block of 64

    wmma::fragment<wmma::accumulator, 16, 16, 16, float> acc[2][4];
#pragma unroll
    for (int mi = 0; mi < 2; ++mi)
#pragma unroll
        for (int ni = 0; ni < 4; ++ni) wmma::fill_fragment(acc[mi][ni], 0.0f);

    for (int k0 = 0; k0 < CI; k0 += BK) {
        __syncthreads();
        // A tiles: 128x16 floats -> hi/lo bf16
#pragma unroll
        for (int it = 0; it < 2; ++it) {
            int idx = tid + it * 256;      // 0..511
            int r = idx >> 2;
            int c = (idx & 3) << 2;
            float4 v = *(const float4*)&A1[(row0 + r) * CI + k0 + c];
            split2(v.x, As1h[r * ALD + c + 0], As1l[r * ALD + c + 0]);
            split2(v.y, As1h[r * ALD + c + 1], As1l[r * ALD + c + 1]);
            split2(v.z, As1h[r * ALD + c + 2], As1l[r * ALD + c + 2]);
            split2(v.w, As1h[r * ALD + c + 3], As1l[r * ALD + c + 3]);
            if constexpr (TWO) {
                float4 u = *(const float4*)&A2[(row0 + r) * CI + k0 + c];
                split2(u.x, As2h[r * ALD + c + 0], As2l[r * ALD + c + 0]);
                split2(u.y, As2h[r * ALD + c + 1], As2l[r * ALD + c + 1]);
                split2(u.z, As2h[r * ALD + c + 2], As2l[r * ALD + c + 2]);
                split2(u.w, As2h[r * ALD + c + 3], As2l[r * ALD + c + 3]);
            }
        }
        // W tiles: 16x128 floats -> hi/lo bf16
#pragma unroll
        for (int it = 0; it < 2; ++it) {
            int idx = tid + it * 256;      // 0..511
            int r = idx >> 5;
            int c = (idx & 31) << 2;
            float4 v = *(const float4*)&Wa[(k0 + r) * CI + c];
            split2(v.x, Ws1h[r * WLD + c + 0], Ws1l[r * WLD + c + 0]);
            split2(v.y, Ws1h[r * WLD + c + 1], Ws1l[r * WLD + c + 1]);
            split2(v.z, Ws1h[r * WLD + c + 2], Ws1l[r * WLD + c + 2]);
            split2(v.w, Ws1h[r * WLD + c + 3], Ws1l[r * WLD + c + 3]);
            if constexpr (TWO) {
                float4 u = *(const float4*)&Wb[(k0 + r) * CI + c];
                split2(u.x, Ws2h[r * WLD + c + 0], Ws2l[r * WLD + c + 0]);
                split2(u.y, Ws2h[r * WLD + c + 1], Ws2l[r * WLD + c + 1]);
                split2(u.z, Ws2h[r * WLD + c + 2], Ws2l[r * WLD + c + 2]);
                split2(u.w, Ws2h[r * WLD + c + 3], Ws2l[r * WLD + c + 3]);
            }
        }
        __syncthreads();

        {
            wmma::fragment<wmma::matrix_a, 16, 16, 16, __nv_bfloat16, wmma::row_major> ah[2], al[2];
            wmma::fragment<wmma::matrix_b, 16, 16, 16, __nv_bfloat16, wmma::row_major> bh[4], bl[4];
#pragma unroll
            for (int mi = 0; mi < 2; ++mi) {
                wmma::load_matrix_sync(ah[mi], &As1h[(wm * 32 + mi * 16) * ALD], ALD);
                wmma::load_matrix_sync(al[mi], &As1l[(wm * 32 + mi * 16) * ALD], ALD);
            }
#pragma unroll
            for (int ni = 0; ni < 4; ++ni) {
                wmma::load_matrix_sync(bh[ni], &Ws1h[wn * 64 + ni * 16], WLD);
                wmma::load_matrix_sync(bl[ni], &Ws1l[wn * 64 + ni * 16], WLD);
            }
#pragma unroll
            for (int mi = 0; mi < 2; ++mi)
#pragma unroll
                for (int ni = 0; ni < 4; ++ni) {
                    wmma::mma_sync(acc[mi][ni], ah[mi], bh[ni], acc[mi][ni]);
                    wmma::mma_sync(acc[mi][ni], ah[mi], bl[ni], acc[mi][ni]);
                    wmma::mma_sync(acc[mi][ni], al[mi], bh[ni], acc[mi][ni]);
                }
            if constexpr (TWO) {
#pragma unroll
                for (int mi = 0; mi < 2; ++mi) {
                    wmma::load_matrix_sync(ah[mi], &As2h[(wm * 32 + mi * 16) * ALD], ALD);
                    wmma::load_matrix_sync(al[mi], &As2l[(wm * 32 + mi * 16) * ALD], ALD);
                }
#pragma unroll
                for (int ni = 0; ni < 4; ++ni) {
                    wmma::load_matrix_sync(bh[ni], &Ws2h[wn * 64 + ni * 16], WLD);
                    wmma::load_matrix_sync(bl[ni], &Ws2l[wn * 64 + ni * 16], WLD);
                }
#pragma unroll
                for (int mi = 0; mi < 2; ++mi)
#pragma unroll
                    for (int ni = 0; ni < 4; ++ni) {
                        wmma::mma_sync(acc[mi][ni], ah[mi], bh[ni], acc[mi][ni]);
                        wmma::mma_sync(acc[mi][ni], ah[mi], bl[ni], acc[mi][ni]);
                        wmma::mma_sync(acc[mi][ni], al[mi], bh[ni], acc[mi][ni]);
                    }
            }
        }
    }

#pragma unroll
    for (int mi = 0; mi < 2; ++mi)
#pragma unroll
        for (int ni = 0; ni < 4; ++ni)
            wmma::store_matrix_sync(&out[(row0 + wm * 32 + mi * 16) * CI + wn * 64 + ni * 16],
                                    acc[mi][ni], CI, wmma::mem_row_major);
}

// ---------------- epilogues ----------------
// GNN layer: buf = relu(buf + b3 + t1*c1 + t2*c2), in place
__global__ void k_epi_gnn(int layer, int osel, const float* __restrict__ b3) {
    int i4 = blockIdx.x * blockDim.x + threadIdx.x;
    if (i4 >= NN * 32) return;
    float4* buf = (float4*)(osel ? g_h1 : g_h0);
    int row = i4 >> 5;
    int j = (i4 & 31) * 4;
    float t1 = g_t1[row], t2 = g_t2[row];
    const float* c1 = g_c1 + layer * CI;
    const float* c2 = g_c2 + layer * CI;
    float4 v = buf[i4];
    v.x = fmaxf(v.x + b3[j + 0] + t1 * c1[j + 0] + t2 * c2[j + 0], 0.f);
    v.y = fmaxf(v.y + b3[j + 1] + t1 * c1[j + 1] + t2 * c2[j + 1], 0.f);
    v.z = fmaxf(v.z + b3[j + 2] + t1 * c1[j + 2] + t2 * c2[j + 2], 0.f);
    v.w = fmaxf(v.w + b3[j + 3] + t1 * c1[j + 3] + t2 * c2[j + 3], 0.f);
    buf[i4] = v;
}

// plain: buf = [relu](buf + bias), in place.  bufsel: 2=g_agg1, 3=g_v0, 4=g_v1
__global__ void k_epi_plain(int bufsel, const float* __restrict__ bias, int relu, int n4) {
    int i4 = blockIdx.x * blockDim.x + threadIdx.x;
    if (i4 >= n4) return;
    float4* buf = (float4*)((bufsel == 2) ? g_agg1 : (bufsel == 3) ? g_v0 : g_v1);
    int j = (i4 & 31) * 4;
    float4 v = buf[i4];
    v.x += bias[j + 0]; v.y += bias[j + 1]; v.z += bias[j + 2]; v.w += bias[j + 3];
    if (relu) {
        v.x = fmaxf(v.x, 0.f); v.y = fmaxf(v.y, 0.f);
        v.z = fmaxf(v.z, 0.f); v.w = fmaxf(v.w, 0.f);
    }
    buf[i4] = v;
}

// ---------------- heads ----------------
__global__ void k_logits(const int* __restrict__ snd, const int* __restrict__ rcv,
                         float* __restrict__ out) {
    int e = (blockIdx.x * blockDim.x + threadIdx.x) >> 5;
    if (e >= EM) return;
    int lane = threadIdx.x & 31;
    const float4* lg = (const float4*)g_agg1;
    float4 a = lg[snd[e] * 32 + lane];
    float4 b = lg[rcv[e] * 32 + lane];
    float d = a.x * b.x + a.y * b.y + a.z * b.z + a.w * b.w;
#pragma unroll
    for (int off = 16; off > 0; off >>= 1) d += __shfl_xor_sync(0xffffffffu, d, off);
    if (lane == 0) out[e] = d;
}

__global__ void k_v0(const int* __restrict__ n_node) {
    int g = (blockIdx.x * blockDim.x + threadIdx.x) >> 5;
    if (g >= NB) return;
    int lane = threadIdx.x & 31;
    const float4* h = (const float4*)g_h1;
    int nn0 = n_node[0];
    float4 acc = make_float4(0.f, 0.f, 0.f, 0.f);
    for (int i = 0; i < NPG; ++i) {
        int gi = g * NPG + i;
        if (gi % nn0 == 0) continue;
        float4 v = h[gi * 32 + lane];
        acc.x += v.x; acc.y += v.y; acc.z += v.z; acc.w += v.w;
    }
    float inv = 1.f / (float)(n_node[g] - 1);
    ((float4*)g_v0)[g * 32 + lane] =
        make_float4(acc.x * inv, acc.y * inv, acc.z * inv, acc.w * inv);
}

__global__ void k_vout(const float* __restrict__ w_out, const float* __restrict__ b_out,
                       float* __restrict__ out) {
    int g = (blockIdx.x * blockDim.x + threadIdx.x) >> 5;
    if (g >= NB) return;
    int lane = threadIdx.x & 31;
    float d = 0.f;
#pragma unroll
    for (int c = lane; c < CI; c += 32) d += g_v1[g * CI + c] * w_out[c];
#pragma unroll
    for (int off = 16; off > 0; off >>= 1) d += __shfl_xor_sync(0xffffffffu, d, off);
    if (lane == 0) out[g] = tanhf(d + b_out[0]);
}

// ---------------- launch ----------------
extern "C" void kernel_launch(void* const* d_in, const int* in_sizes, int n_in,
                              void* d_out, int out_size) {
    const int*   nodes     = (const int*)d_in[0];
    const int*   senders   = (const int*)d_in[1];
    const int*   receivers = (const int*)d_in[2];
    const int*   gsnd      = (const int*)d_in[3];
    const int*   grcv      = (const int*)d_in[4];
    const int*   n_node    = (const int*)d_in[5];
    const float* emb       = (const float*)d_in[6];
    const float* w1        = (const float*)d_in[7];
    const float* b1        = (const float*)d_in[8];
    const float* w2        = (const float*)d_in[9];
    const float* b2        = (const float*)d_in[10];
    const float* w3        = (const float*)d_in[11];
    const float* b3        = (const float*)d_in[12];
    const float* w_logit   = (const float*)d_in[13];
    const float* b_logit   = (const float*)d_in[14];
    const float* eval_w    = (const float*)d_in[15];
    const float* eval_b    = (const float*)d_in[16];
    const float* w_out     = (const float*)d_in[17];
    const float* b_out     = (const float*)d_in[18];
    float* out = (float*)d_out;

    k_zero_counts<<<NN / 256, 256>>>();
    k_hist<<<EM / 256, 256>>>(senders, receivers, 1, EM);
    k_hist<<<EGRID / 256, 256>>>(gsnd, grcv, 2, EGRID);
    k_norm<<<NN / 256, 256>>>(1);
    k_norm<<<NN / 256, 256>>>(2);

    // CSR for move graph
    k_scan1<<<256, 256>>>(1);
    k_scan2<<<1, 256>>>();
    k_scan3<<<256, 256>>>(1, EM);
    k_cursor<<<NN / 256, 256>>>(1);
    k_fill<<<EM / 256, 256>>>(senders, receivers, 1, EM);
    // CSR for grid graph
    k_scan1<<<256, 256>>>(2);
    k_scan2<<<1, 256>>>();
    k_scan3<<<256, 256>>>(2, EGRID);
    k_cursor<<<NN / 256, 256>>>(2);
    k_fill<<<EGRID / 256, 256>>>(gsnd, grcv, 2, EGRID);

    k_tnorm<<<NN / 256, 256>>>(1);
    k_tnorm<<<NN / 256, 256>>>(2);
    k_fuse<<<NLAYER * CI, CI>>>(w1, w2, b1, b2, w3);
    k_embed<<<(NN * 32) / 256, 256>>>(nodes, (const float4*)emb);

    for (int i = 0; i < NLAYER; ++i) {
        k_agg_both<<<(2 * NN) / 8, 256>>>(i & 1);
        k_gemm_tc<true><<<NN / 128, 256>>>(i, 0, 1 - (i & 1), nullptr);
        k_epi_gnn<<<(NN * 32) / 256, 256>>>(i, 1 - (i & 1), b3 + i * CI);
    }

    // logits head: lg = h @ w_logit + b_logit  -> g_agg1
    k_gemm_tc<false><<<NN / 128, 256>>>(0, 1, 2, w_logit);
    k_epi_plain<<<(NN * 32) / 256, 256>>>(2, b_logit, 0, NN * 32);
    k_logits<<<EM / 8, 256>>>(senders, receivers, out);

    // value head
    k_v0<<<NB / 8, 256>>>(n_node);
    for (int l = 0; l < NEVAL; ++l) {
        k_gemm_tc<false><<<NB / 128, 256>>>(0, 2 + (l & 1), 4 - (l & 1),
                                            eval_w + l * CI * CI);
        k_epi_plain<<<(NB * 32) / 256, 256>>>(4 - (l & 1), eval_b + l * CI, 1, NB * 32);
    }
    k_vout<<<NB / 8, 256>>>(w_out, b_out, out + EM);
}

// round 15
// speedup vs baseline: 1.2929x; 1.0669x over previous
#include <cuda_runtime.h>
#include <cuda_bf16.h>
#include <mma.h>
using namespace nvcuda;

#define NN     65536
#define EM     2097152
#define EGRID  524288
#define CI     128
#define NB     1024
#define NPG    64
#define NLAYER 7
#define NEVAL  5

// ---------------- scratch (device globals: allocation-free) ----------------
__device__ float g_h0[NN * CI];
__device__ float g_h1[NN * CI];
__device__ float g_agg1[NN * CI];
__device__ float g_agg2[NN * CI];
__device__ int   g_cnts1[NN];
__device__ int   g_cnts2[NN];
__device__ int   g_cntR[2 * NN];          // receiver counts, both graphs
__device__ int   g_rowptr1[NN + 1];
__device__ int   g_rowptr2[NN + 1];
__device__ int   g_cursor1[NN];
__device__ int   g_cursor2[NN];
__device__ int   g_col1[EM];
__device__ int   g_col2[EGRID];
__device__ float g_s1[NN], g_r1[NN], g_s2[NN], g_r2[NN], g_t1[NN], g_t2[NN];
__device__ __align__(16) __nv_bfloat16 g_W13h[NLAYER * CI * CI];
__device__ __align__(16) __nv_bfloat16 g_W13l[NLAYER * CI * CI];
__device__ __align__(16) __nv_bfloat16 g_W23h[NLAYER * CI * CI];
__device__ __align__(16) __nv_bfloat16 g_W23l[NLAYER * CI * CI];
__device__ __align__(16) __nv_bfloat16 g_Wsh[(1 + NEVAL) * CI * CI];
__device__ __align__(16) __nv_bfloat16 g_Wsl[(1 + NEVAL) * CI * CI];
__device__ float g_c1[NLAYER * CI];
__device__ float g_c2[NLAYER * CI];
__device__ float g_v0[NB * CI];
__device__ float g_v1[NB * CI];
__device__ int   g_bsum[512];

__device__ __forceinline__ void split2(float x, __nv_bfloat16& hi, __nv_bfloat16& lo) {
    hi = __float2bfloat16_rn(x);
    lo = __float2bfloat16_rn(x - __bfloat162float(hi));
}

// ---------------- preprocessing ----------------
__global__ void k_zero() {
    int i = blockIdx.x * blockDim.x + threadIdx.x;
    if (i < NN) { g_cnts1[i] = 0; g_cnts2[i] = 0; }
    if (i < 2 * NN) g_cntR[i] = 0;
}

__global__ void k_hist_all(const int* __restrict__ s1, const int* __restrict__ r1,
                           const int* __restrict__ s2, const int* __restrict__ r2) {
    int i = blockIdx.x * blockDim.x + threadIdx.x;
    if (i < EM) {
        atomicAdd(&g_cnts1[s1[i]], 1);
        atomicAdd(&g_cntR[r1[i]], 1);
    } else {
        int j = i - EM;
        if (j < EGRID) {
            atomicAdd(&g_cnts2[s2[j]], 1);
            atomicAdd(&g_cntR[NN + r2[j]], 1);
        }
    }
}

__global__ void k_norm_all() {
    int i = blockIdx.x * blockDim.x + threadIdx.x;
    if (i >= 2 * NN) return;
    if (i < NN) {
        g_s1[i] = rsqrtf((float)(g_cnts1[i] + 1));
        g_r1[i] = rsqrtf((float)(g_cntR[i] + 1));
    } else {
        int j = i - NN;
        g_s2[j] = rsqrtf((float)(g_cnts2[j] + 1));
        g_r2[j] = rsqrtf((float)(g_cntR[i] + 1));
    }
}

// unified scan over g_cntR[2NN] -> rowptr1, rowptr2
__global__ void k_scan1() {
    __shared__ int sh[256];
    int tid = threadIdx.x;
    sh[tid] = g_cntR[blockIdx.x * 256 + tid];
    __syncthreads();
    for (int off = 128; off > 0; off >>= 1) {
        if (tid < off) sh[tid] += sh[tid + off];
        __syncthreads();
    }
    if (tid == 0) g_bsum[blockIdx.x] = sh[0];
}

__global__ void k_scan2() {   // 512 threads
    __shared__ int sh[512];
    int tid = threadIdx.x;
    int v = g_bsum[tid];
    sh[tid] = v;
    __syncthreads();
    for (int off = 1; off < 512; off <<= 1) {
        int t = 0;
        if (tid >= off) t = sh[tid - off];
        __syncthreads();
        sh[tid] += t;
        __syncthreads();
    }
    g_bsum[tid] = sh[tid] - v;  // exclusive
}

__global__ void k_scan3() {
    __shared__ int sh[256];
    int tid = threadIdx.x;
    int i = blockIdx.x * 256 + tid;
    int v = g_cntR[i];
    sh[tid] = v;
    __syncthreads();
    for (int off = 1; off < 256; off <<= 1) {
        int t = 0;
        if (tid >= off) t = sh[tid - off];
        __syncthreads();
        sh[tid] += t;
        __syncthreads();
    }
    int pref = sh[tid] - v + g_bsum[blockIdx.x];
    if (i < NN) g_rowptr1[i] = pref;
    else        g_rowptr2[i - NN] = pref - EM;
    if (i == 0) { g_rowptr1[NN] = EM; g_rowptr2[NN] = EGRID; }
}

__global__ void k_cursor() {
    int i = blockIdx.x * blockDim.x + threadIdx.x;
    if (i >= 2 * NN) return;
    if (i < NN) g_cursor1[i] = g_rowptr1[i];
    else        g_cursor2[i - NN] = g_rowptr2[i - NN];
}

__global__ void k_fill_all(const int* __restrict__ s1, const int* __restrict__ r1,
                           const int* __restrict__ s2, const int* __restrict__ r2) {
    int i = blockIdx.x * blockDim.x + threadIdx.x;
    if (i < EM) {
        int pos = atomicAdd(&g_cursor1[r1[i]], 1);
        g_col1[pos] = s1[i];
    } else {
        int j = i - EM;
        if (j < EGRID) {
            int pos = atomicAdd(&g_cursor2[r2[j]], 1);
            g_col2[pos] = s2[j];
        }
    }
}

__global__ void k_tnorm_all() {
    int i = blockIdx.x * blockDim.x + threadIdx.x;
    if (i >= 2 * NN) return;
    const int *rowptr, *col; const float *s, *r; float* t; int j;
    if (i < NN) { j = i;      rowptr = g_rowptr1; col = g_col1; s = g_s1; r = g_r1; t = g_t1; }
    else        { j = i - NN; rowptr = g_rowptr2; col = g_col2; s = g_s2; r = g_r2; t = g_t2; }
    float acc = s[j];
    int k1 = rowptr[j + 1];
    for (int k = rowptr[j]; k < k1; ++k) acc += s[col[k]];
    t[j] = r[j] * acc;
}

// W13 = W1 @ W3_top, W23 = W2 @ W3_bot (bf16 hi/lo); c1 = b1@W3_top, c2 = b2@W3_bot
__global__ void k_fuse(const float* __restrict__ w1, const float* __restrict__ w2,
                       const float* __restrict__ b1, const float* __restrict__ b2,
                       const float* __restrict__ w3) {
    int l = blockIdx.x >> 7;
    int k = blockIdx.x & 127;
    int j = threadIdx.x;
    const float* w3l = w3 + l * 2 * CI * CI;
    const float* w1r = w1 + (l * CI + k) * CI;
    const float* w2r = w2 + (l * CI + k) * CI;
    float a1 = 0.f, a2 = 0.f;
    for (int m = 0; m < CI; ++m) {
        a1 += w1r[m] * w3l[m * CI + j];
        a2 += w2r[m] * w3l[(CI + m) * CI + j];
    }
    int idx = (l * CI + k) * CI + j;
    split2(a1, g_W13h[idx], g_W13l[idx]);
    split2(a2, g_W23h[idx], g_W23l[idx]);
    if (k == 0) {
        const float* b1r = b1 + l * CI;
        const float* b2r = b2 + l * CI;
        float c1 = 0.f, c2 = 0.f;
        for (int m = 0; m < CI; ++m) {
            c1 += b1r[m] * w3l[m * CI + j];
            c2 += b2r[m] * w3l[(CI + m) * CI + j];
        }
        g_c1[l * CI + j] = c1;
        g_c2[l * CI + j] = c2;
    }
}

// split w_logit (idx 0) and eval_w (idx 1..5) into bf16 hi/lo
__global__ void k_split_small(const float* __restrict__ w_logit,
                              const float* __restrict__ eval_w) {
    int i = blockIdx.x * blockDim.x + threadIdx.x;
    if (i >= (1 + NEVAL) * CI * CI) return;
    float v = (i < CI * CI) ? w_logit[i] : eval_w[i - CI * CI];
    split2(v, g_Wsh[i], g_Wsl[i]);
}

__global__ void k_embed(const int* __restrict__ nodes, const float4* __restrict__ emb) {
    int i = blockIdx.x * blockDim.x + threadIdx.x;
    if (i >= NN * 32) return;
    int node = i >> 5, c = i & 31;
    ((float4*)g_h0)[i] = emb[nodes[node] * 32 + c];
}

// ---------------- aggregation: warp per node, both graphs in one launch ----------------
__device__ __forceinline__ void agg_node(int gw, int lane, const float4* __restrict__ h,
                                         const int* __restrict__ rowptr,
                                         const int* __restrict__ col,
                                         const float* __restrict__ s,
                                         const float* __restrict__ r,
                                         float4* __restrict__ out) {
    float sv = s[gw];
    float4 hv = h[gw * 32 + lane];
    float ax = sv * hv.x, ay = sv * hv.y, az = sv * hv.z, aw = sv * hv.w;  // self edge
    int k = rowptr[gw], kend = rowptr[gw + 1];
    for (; k + 3 < kend; k += 4) {
        int i0 = col[k], i1 = col[k + 1], i2 = col[k + 2], i3 = col[k + 3];
        float f0 = s[i0], f1 = s[i1], f2 = s[i2], f3 = s[i3];
        float4 h0 = h[i0 * 32 + lane];
        float4 h1 = h[i1 * 32 + lane];
        float4 h2 = h[i2 * 32 + lane];
        float4 h3 = h[i3 * 32 + lane];
        ax += f0 * h0.x + f1 * h1.x + f2 * h2.x + f3 * h3.x;
        ay += f0 * h0.y + f1 * h1.y + f2 * h2.y + f3 * h3.y;
        az += f0 * h0.z + f1 * h1.z + f2 * h2.z + f3 * h3.z;
        aw += f0 * h0.w + f1 * h1.w + f2 * h2.w + f3 * h3.w;
    }
    for (; k < kend; ++k) {
        int i0 = col[k];
        float f0 = s[i0];
        float4 h0 = h[i0 * 32 + lane];
        ax += f0 * h0.x; ay += f0 * h0.y; az += f0 * h0.z; aw += f0 * h0.w;
    }
    float rv = r[gw];
    out[gw * 32 + lane] = make_float4(rv * ax, rv * ay, rv * az, rv * aw);
}

__global__ void k_agg_both(int hsel) {
    int gw = (blockIdx.x * blockDim.x + threadIdx.x) >> 5;
    int lane = threadIdx.x & 31;
    const float4* h = (const float4*)(hsel ? g_h1 : g_h0);
    if (gw < NN) {
        agg_node(gw, lane, h, g_rowptr1, g_col1, g_s1, g_r1, (float4*)g_agg1);
    } else {
        gw -= NN;
        if (gw >= NN) return;
        agg_node(gw, lane, h, g_rowptr2, g_col2, g_s2, g_r2, (float4*)g_agg2);
    }
}

// ---------------- bf16 split tensor-core GEMM (3-MMA compensated) + fused epilogue ----
// out = EPI(A1@Wa [+ A2@Wb]); W pre-split in global bf16 hi/lo; A split per tile.
// EPI: 1 = GNN (bias + t1*c1 + t2*c2, relu), 2 = bias only, 3 = bias + relu.
// Epilogue: per-warp store_matrix_sync to smem staging (API-defined row-major
// layout), apply epilogue, write float4 to global. Staging aliases dead A tiles.
template <bool TWO, int EPI>
__global__ __launch_bounds__(256)
void k_gemm_tc(int layer, int asel, int osel, int wsel, const float* __restrict__ bias) {
    constexpr int BK  = 16;
    constexpr int ALD = 24;
    constexpr int WLD = 136;
    __shared__ __align__(16) __nv_bfloat16 As1[2][128 * ALD];          // [0]=hi, [1]=lo
    __shared__ __align__(16) __nv_bfloat16 Ws1[2][BK * WLD];
    __shared__ __align__(16) __nv_bfloat16 As2[TWO ? 2 : 1][TWO ? 128 * ALD : 8];
    __shared__ __align__(16) __nv_bfloat16 Ws2[TWO ? 2 : 1][TWO ? BK * WLD : 8];

    const float* A1;
    const float* A2 = nullptr;
    const __nv_bfloat16 *Wah, *Wal, *Wbh = nullptr, *Wbl = nullptr;
    if constexpr (TWO) {
        A1 = g_agg1; A2 = g_agg2;
        Wah = g_W13h + layer * CI * CI; Wal = g_W13l + layer * CI * CI;
        Wbh = g_W23h + layer * CI * CI; Wbl = g_W23l + layer * CI * CI;
    } else {
        A1 = (asel == 1) ? g_h1 : (asel == 2) ? g_v0 : g_v1;
        Wah = g_Wsh + wsel * CI * CI; Wal = g_Wsl + wsel * CI * CI;
    }
    float* out = (osel == 0) ? g_h0 : (osel == 1) ? g_h1 : (osel == 2) ? g_agg1
               : (osel == 3) ? g_v0 : g_v1;

    int tid  = threadIdx.x;
    int lane = tid & 31;
    int row0 = blockIdx.x * 128;
    int wid  = tid >> 5;
    int wm   = wid & 3;
    int wn   = wid >> 2;

    wmma::fragment<wmma::accumulator, 16, 16, 16, float> acc[2][4];
#pragma unroll
    for (int mi = 0; mi < 2; ++mi)
#pragma unroll
        for (int ni = 0; ni < 4; ++ni) wmma::fill_fragment(acc[mi][ni], 0.0f);

    for (int k0 = 0; k0 < CI; k0 += BK) {
        __syncthreads();
        // A tiles: 128x16 floats -> hi/lo bf16
#pragma unroll
        for (int it = 0; it < 2; ++it) {
            int idx = tid + it * 256;
            int r = idx >> 2;
            int c = (idx & 3) << 2;
            float4 v = *(const float4*)&A1[(row0 + r) * CI + k0 + c];
            split2(v.x, As1[0][r * ALD + c + 0], As1[1][r * ALD + c + 0]);
            split2(v.y, As1[0][r * ALD + c + 1], As1[1][r * ALD + c + 1]);
            split2(v.z, As1[0][r * ALD + c + 2], As1[1][r * ALD + c + 2]);
            split2(v.w, As1[0][r * ALD + c + 3], As1[1][r * ALD + c + 3]);
            if constexpr (TWO) {
                float4 u = *(const float4*)&A2[(row0 + r) * CI + k0 + c];
                split2(u.x, As2[0][r * ALD + c + 0], As2[1][r * ALD + c + 0]);
                split2(u.y, As2[0][r * ALD + c + 1], As2[1][r * ALD + c + 1]);
                split2(u.z, As2[0][r * ALD + c + 2], As2[1][r * ALD + c + 2]);
                split2(u.w, As2[0][r * ALD + c + 3], As2[1][r * ALD + c + 3]);
            }
        }
        // W tiles: pre-split bf16, direct copy (4 elems = 8B per slot)
#pragma unroll
        for (int it = 0; it < 2; ++it) {
            int idx = tid + it * 256;
            int r = idx >> 5;
            int c = (idx & 31) << 2;
            *(uint2*)&Ws1[0][r * WLD + c] = *(const uint2*)&Wah[(k0 + r) * CI + c];
            *(uint2*)&Ws1[1][r * WLD + c] = *(const uint2*)&Wal[(k0 + r) * CI + c];
            if constexpr (TWO) {
                *(uint2*)&Ws2[0][r * WLD + c] = *(const uint2*)&Wbh[(k0 + r) * CI + c];
                *(uint2*)&Ws2[1][r * WLD + c] = *(const uint2*)&Wbl[(k0 + r) * CI + c];
            }
        }
        __syncthreads();

        {
            wmma::fragment<wmma::matrix_a, 16, 16, 16, __nv_bfloat16, wmma::row_major> ah[2], al[2];
            wmma::fragment<wmma::matrix_b, 16, 16, 16, __nv_bfloat16, wmma::row_major> bh[4], bl[4];
#pragma unroll
            for (int mi = 0; mi < 2; ++mi) {
                wmma::load_matrix_sync(ah[mi], &As1[0][(wm * 32 + mi * 16) * ALD], ALD);
                wmma::load_matrix_sync(al[mi], &As1[1][(wm * 32 + mi * 16) * ALD], ALD);
            }
#pragma unroll
            for (int ni = 0; ni < 4; ++ni) {
                wmma::load_matrix_sync(bh[ni], &Ws1[0][wn * 64 + ni * 16], WLD);
                wmma::load_matrix_sync(bl[ni], &Ws1[1][wn * 64 + ni * 16], WLD);
            }
#pragma unroll
            for (int mi = 0; mi < 2; ++mi)
#pragma unroll
                for (int ni = 0; ni < 4; ++ni) {
                    wmma::mma_sync(acc[mi][ni], ah[mi], bh[ni], acc[mi][ni]);
                    wmma::mma_sync(acc[mi][ni], ah[mi], bl[ni], acc[mi][ni]);
                    wmma::mma_sync(acc[mi][ni], al[mi], bh[ni], acc[mi][ni]);
                }
            if constexpr (TWO) {
#pragma unroll
                for (int mi = 0; mi < 2; ++mi) {
                    wmma::load_matrix_sync(ah[mi], &As2[0][(wm * 32 + mi * 16) * ALD], ALD);
                    wmma::load_matrix_sync(al[mi], &As2[1][(wm * 32 + mi * 16) * ALD], ALD);
                }
#pragma unroll
                for (int ni = 0; ni < 4; ++ni) {
                    wmma::load_matrix_sync(bh[ni], &Ws2[0][wn * 64 + ni * 16], WLD);
                    wmma::load_matrix_sync(bl[ni], &Ws2[1][wn * 64 + ni * 16], WLD);
                }
#pragma unroll
                for (int mi = 0; mi < 2; ++mi)
#pragma unroll
                    for (int ni = 0; ni < 4; ++ni) {
                        wmma::mma_sync(acc[mi][ni], ah[mi], bh[ni], acc[mi][ni]);
                        wmma::mma_sync(acc[mi][ni], ah[mi], bl[ni], acc[mi][ni]);
                        wmma::mma_sync(acc[mi][ni], al[mi], bh[ni], acc[mi][ni]);
                    }
            }
        }
    }

    // -------- fused epilogue: stage each 16x16 fragment in smem, apply, store --------
    __syncthreads();                         // A tiles dead for ALL warps; safe to alias
    float* stg = ((float*)As1) + wid * 256;  // 1KB per warp, 8KB total (< 12KB of As1)
    const float* c1p = (EPI == 1) ? (g_c1 + layer * CI) : nullptr;
    const float* c2p = (EPI == 1) ? (g_c2 + layer * CI) : nullptr;

#pragma unroll
    for (int mi = 0; mi < 2; ++mi)
#pragma unroll
        for (int ni = 0; ni < 4; ++ni) {
            wmma::store_matrix_sync(stg, acc[mi][ni], 16, wmma::mem_row_major);
            __syncwarp();
            int rbase = row0 + wm * 32 + mi * 16;
            int cbase = wn * 64 + ni * 16;
#pragma unroll
            for (int e4 = lane; e4 < 64; e4 += 32) {
                int r  = e4 >> 2;
                int c  = (e4 & 3) << 2;
                float4 v = *(float4*)&stg[r * 16 + c];
                int grow = rbase + r;
                int gcol = cbase + c;
                if constexpr (EPI == 1) {
                    float t1 = g_t1[grow], t2 = g_t2[grow];
                    v.x = fmaxf(v.x + bias[gcol + 0] + t1 * c1p[gcol + 0] + t2 * c2p[gcol + 0], 0.f);
                    v.y = fmaxf(v.y + bias[gcol + 1] + t1 * c1p[gcol + 1] + t2 * c2p[gcol + 1], 0.f);
                    v.z = fmaxf(v.z + bias[gcol + 2] + t1 * c1p[gcol + 2] + t2 * c2p[gcol + 2], 0.f);
                    v.w = fmaxf(v.w + bias[gcol + 3] + t1 * c1p[gcol + 3] + t2 * c2p[gcol + 3], 0.f);
                } else if constexpr (EPI == 2) {
                    v.x += bias[gcol + 0]; v.y += bias[gcol + 1];
                    v.z += bias[gcol + 2]; v.w += bias[gcol + 3];
                } else if constexpr (EPI == 3) {
                    v.x = fmaxf(v.x + bias[gcol + 0], 0.f);
                    v.y = fmaxf(v.y + bias[gcol + 1], 0.f);
                    v.z = fmaxf(v.z + bias[gcol + 2], 0.f);
                    v.w = fmaxf(v.w + bias[gcol + 3], 0.f);
                }
                *(float4*)&out[grow * CI + gcol] = v;
            }
            __syncwarp();
        }
}

// ---------------- heads ----------------
__global__ void k_logits(const int* __restrict__ snd, const int* __restrict__ rcv,
                         float* __restrict__ out) {
    int e = (blockIdx.x * blockDim.x + threadIdx.x) >> 5;
    if (e >= EM) return;
    int lane = threadIdx.x & 31;
    const float4* lg = (const float4*)g_agg1;
    float4 a = lg[snd[e] * 32 + lane];
    float4 b = lg[rcv[e] * 32 + lane];
    float d = a.x * b.x + a.y * b.y + a.z * b.z + a.w * b.w;
#pragma unroll
    for (int off = 16; off > 0; off >>= 1) d += __shfl_xor_sync(0xffffffffu, d, off);
    if (lane == 0) out[e] = d;
}

__global__ void k_v0(const int* __restrict__ n_node) {
    int g = (blockIdx.x * blockDim.x + threadIdx.x) >> 5;
    if (g >= NB) return;
    int lane = threadIdx.x & 31;
    const float4* h = (const float4*)g_h1;
    int nn0 = n_node[0];
    float4 acc = make_float4(0.f, 0.f, 0.f, 0.f);
    for (int i = 0; i < NPG; ++i) {
        int gi = g * NPG + i;
        if (gi % nn0 == 0) continue;
        float4 v = h[gi * 32 + lane];
        acc.x += v.x; acc.y += v.y; acc.z += v.z; acc.w += v.w;
    }
    float inv = 1.f / (float)(n_node[g] - 1);
    ((float4*)g_v0)[g * 32 + lane] =
        make_float4(acc.x * inv, acc.y * inv, acc.z * inv, acc.w * inv);
}

__global__ void k_vout(const float* __restrict__ w_out, const float* __restrict__ b_out,
                       float* __restrict__ out) {
    int g = (blockIdx.x * blockDim.x + threadIdx.x) >> 5;
    if (g >= NB) return;
    int lane = threadIdx.x & 31;
    float d = 0.f;
#pragma unroll
    for (int c = lane; c < CI; c += 32) d += g_v1[g * CI + c] * w_out[c];
#pragma unroll
    for (int off = 16; off > 0; off >>= 1) d += __shfl_xor_sync(0xffffffffu, d, off);
    if (lane == 0) out[g] = tanhf(d + b_out[0]);
}

// ---------------- launch ----------------
extern "C" void kernel_launch(void* const* d_in, const int* in_sizes, int n_in,
                              void* d_out, int out_size) {
    const int*   nodes     = (const int*)d_in[0];
    const int*   senders   = (const int*)d_in[1];
    const int*   receivers = (const int*)d_in[2];
    const int*   gsnd      = (const int*)d_in[3];
    const int*   grcv      = (const int*)d_in[4];
    const int*   n_node    = (const int*)d_in[5];
    const float* emb       = (const float*)d_in[6];
    const float* w1        = (const float*)d_in[7];
    const float* b1        = (const float*)d_in[8];
    const float* w2        = (const float*)d_in[9];
    const float* b2        = (const float*)d_in[10];
    const float* w3        = (const float*)d_in[11];
    const float* b3        = (const float*)d_in[12];
    const float* w_logit   = (const float*)d_in[13];
    const float* b_logit   = (const float*)d_in[14];
    const float* eval_w    = (const float*)d_in[15];
    const float* eval_b    = (const float*)d_in[16];
    const float* w_out     = (const float*)d_in[17];
    const float* b_out     = (const float*)d_in[18];
    float* out = (float*)d_out;

    const int ETOT = EM + EGRID;

    k_zero<<<(2 * NN) / 256, 256>>>();
    k_hist_all<<<ETOT / 256, 256>>>(senders, receivers, gsnd, grcv);
    k_norm_all<<<(2 * NN) / 256, 256>>>();
    k_scan1<<<512, 256>>>();
    k_scan2<<<1, 512>>>();
    k_scan3<<<512, 256>>>();
    k_cursor<<<(2 * NN) / 256, 256>>>();
    k_fill_all<<<ETOT / 256, 256>>>(senders, receivers, gsnd, grcv);
    k_tnorm_all<<<(2 * NN) / 256, 256>>>();
    k_fuse<<<NLAYER * CI, CI>>>(w1, w2, b1, b2, w3);
    k_split_small<<<((1 + NEVAL) * CI * CI) / 256, 256>>>(w_logit, eval_w);
    k_embed<<<(NN * 32) / 256, 256>>>(nodes, (const float4*)emb);

    for (int i = 0; i < NLAYER; ++i) {
        k_agg_both<<<(2 * NN) / 8, 256>>>(i & 1);
        k_gemm_tc<true, 1><<<NN / 128, 256>>>(i, 0, 1 - (i & 1), 0, b3 + i * CI);
    }

    // logits head: lg = h @ w_logit + b_logit (fused) -> g_agg1
    k_gemm_tc<false, 2><<<NN / 128, 256>>>(0, 1, 2, 0, b_logit);
    k_logits<<<EM / 8, 256>>>(senders, receivers, out);

    // value head
    k_v0<<<NB / 8, 256>>>(n_node);
    for (int l = 0; l < NEVAL; ++l) {
        k_gemm_tc<false, 3><<<NB / 128, 256>>>(0, 2 + (l & 1), 4 - (l & 1), 1 + l,
                                               eval_b + l * CI);
    }
    k_vout<<<NB / 8, 256>>>(w_out, b_out, out + EM);
}